// round 5
// baseline (speedup 1.0000x reference)
#include <cuda_runtime.h>
#include <cuda_fp16.h>
#include <cstdint>

// Problem constants
static constexpr int N_CELL  = 50000;
static constexpr int N_NET   = 10000;
static constexpr int N_GCELL = 20000;
static constexpr int E       = 100000;
static constexpr int D       = 32;
static constexpr int N_PTOT  = N_NET + N_GCELL;                    // 30000 P rows

// Degree-counter layout
static constexpr int OFF_PINS_S   = 0;
static constexpr int OFF_PINS_D   = OFF_PINS_S + N_CELL;
static constexpr int OFF_CON_S    = OFF_PINS_D + N_NET;
static constexpr int OFF_CON_D    = OFF_CON_S + N_GCELL;
static constexpr int OFF_PT_S     = OFF_CON_D + N_GCELL;
static constexpr int OFF_PT_D     = OFF_PT_S + N_CELL;
static constexpr int OFF_PINNED_D = OFF_PT_D + N_GCELL;
static constexpr int OFF_PF_D     = OFF_PINNED_D + N_CELL;
static constexpr int DEG_TOTAL    = OFF_PF_D + N_CELL;             // 270000

// Scratch
__device__ int    g_deg[DEG_TOTAL];
__device__ float  g_feat_pins[N_CELL * D];
__device__ float  g_feat_pt[N_CELL * D];
__device__ float  g_feat_connect[N_GCELL * D];
__device__ __align__(16) __half g_P[(size_t)N_PTOT * 544];   // fp16 NNConv factor

// ---------------------------------------------------------------------------
// f32x2 packed-FMA helpers (Blackwell FFMA2)
typedef unsigned long long ull;
__device__ __forceinline__ ull f2pack(float lo, float hi) {
    ull r; asm("mov.b64 %0, {%1,%2};" : "=l"(r) : "f"(lo), "f"(hi)); return r;
}
__device__ __forceinline__ void f2unpack(ull v, float& lo, float& hi) {
    asm("mov.b64 {%0,%1}, %2;" : "=f"(lo), "=f"(hi) : "l"(v));
}
__device__ __forceinline__ ull ffma2(ull a, ull b, ull c) {
    ull d; asm("fma.rn.f32x2 %0, %1, %2, %3;" : "=l"(d) : "l"(a), "l"(b), "l"(c)); return d;
}

// NOTE: no "memory" clobber — nothing in-kernel ever reads the red target,
// and removing it lets the compiler hoist independent gathers above reductions.
__device__ __forceinline__ void red_add_v4(float* addr, float x, float y, float z, float w) {
    asm volatile("red.global.add.v4.f32 [%0], {%1,%2,%3,%4};"
                 :: "l"(addr), "f"(x), "f"(y), "f"(z), "f"(w));
}

// 8 halves (16B) -> 4 packed f32x2
struct F8 { ull v[4]; };
__device__ __forceinline__ F8 ldh8(const __half* p) {
    uint4 u = __ldg(reinterpret_cast<const uint4*>(p));
    unsigned uu[4] = {u.x, u.y, u.z, u.w};
    F8 r;
#pragma unroll
    for (int i = 0; i < 4; i++) {
        __half2 h = *reinterpret_cast<__half2*>(&uu[i]);
        float2 f = __half22float2(h);
        r.v[i] = f2pack(f.x, f.y);
    }
    return r;
}

// ---------------------------------------------------------------------------
// K1: zero degree counters + bias-init cell & gcell output regions
// (out_net region is fully overwritten by the dense kernel.)
static constexpr int INIT_TOTAL = (N_CELL + N_GCELL) * D;   // 2.24M
__global__ void init_kernel(float* __restrict__ out,
                            const float* __restrict__ b_pinned,
                            const float* __restrict__ b_pf,
                            const float* __restrict__ b_connect,
                            const float* __restrict__ b_pt) {
    int idx = blockIdx.x * blockDim.x + threadIdx.x;
    if (idx < DEG_TOTAL) g_deg[idx] = 0;
    if (idx >= INIT_TOTAL) return;
    int row = idx >> 5;
    int j = idx & 31;
    if (row < N_CELL) out[idx] = b_pinned[j] + b_pf[j];
    else              out[(size_t)(row + N_NET) * 32 + j] = b_connect[j] + b_pt[j];
}

// ---------------------------------------------------------------------------
// K2: degree counting (first DEG_B blocks) + all dense GEMMs (rest).
// Dense is degree-independent (all norm applied in the edge kernel).
static constexpr int DEG_B   = (E + 255) / 256;        // 391
static constexpr int NT_P    = (N_PTOT + 31) / 32;     // 938
static constexpr int NB_P    = NT_P * 5;               // 4690
static constexpr int NT_DUAL = (N_CELL + 31) / 32;     // 1563
static constexpr int NT_CON  = (N_GCELL + 31) / 32;    // 625
static constexpr int NT_NET  = (N_NET + 31) / 32;      // 313
static constexpr int NB_DENSE = NB_P + NT_DUAL + NT_CON + NT_NET;
static constexpr int NB_WORK  = DEG_B + NB_DENSE;

__global__ __launch_bounds__(256) void work_kernel(
        const float* __restrict__ node_feat,
        const float* __restrict__ net_feat,
        const float* __restrict__ hanna_feat,
        const float* __restrict__ W_topo, const float* __restrict__ b_topo,
        const float* __restrict__ W_pins, const float* __restrict__ W_pt,
        const float* __restrict__ W_connect, const float* __restrict__ W_net,
        const float* __restrict__ b_pins, const float* __restrict__ b_net,
        const int* __restrict__ pins_src, const int* __restrict__ pins_dst,
        const int* __restrict__ connect_src, const int* __restrict__ connect_dst,
        const int* __restrict__ pt_src, const int* __restrict__ pt_dst,
        const int* __restrict__ pinned_dst, const int* __restrict__ pf_dst,
        float* __restrict__ out_net) {
    __shared__ ull Asm2[32 * 33];    // (a,a) packed A tile
    __shared__ ull Wsm2[32 * 64];    // paired W columns

    int bid = blockIdx.x;
    int tid = threadIdx.x;

    // ---- degree blocks ----
    if (bid < DEG_B) {
        int e = bid * 256 + tid;
        if (e >= E) return;
        atomicAdd(&g_deg[OFF_PINS_S   + pins_src[e]], 1);
        atomicAdd(&g_deg[OFF_PINS_D   + pins_dst[e]], 1);
        atomicAdd(&g_deg[OFF_CON_S    + connect_src[e]], 1);
        atomicAdd(&g_deg[OFF_CON_D    + connect_dst[e]], 1);
        atomicAdd(&g_deg[OFF_PT_S     + pt_src[e]], 1);
        atomicAdd(&g_deg[OFF_PT_D     + pt_dst[e]], 1);
        atomicAdd(&g_deg[OFF_PINNED_D + pinned_dst[e]], 1);
        atomicAdd(&g_deg[OFF_PF_D     + pf_dst[e]], 1);
        return;
    }
    bid -= DEG_B;

    int jobtype, tile, grp = 0;
    if (bid < NB_P)                        { jobtype = 0; tile = bid / 5; grp = bid % 5; }
    else if (bid < NB_P + NT_DUAL)         { jobtype = 1; tile = bid - NB_P; }
    else if (bid < NB_P + NT_DUAL + NT_CON){ jobtype = 2; tile = bid - NB_P - NT_DUAL; }
    else                                   { jobtype = 3; tile = bid - NB_P - NT_DUAL - NT_CON; }

    int n0 = tile * 32;
    int nrows = (jobtype == 0) ? N_PTOT : (jobtype == 1) ? N_CELL : (jobtype == 2) ? N_GCELL : N_NET;

    // ---- stage A (packed (a,a)) ----
    for (int idx = tid; idx < 32 * 32; idx += 256) {
        int r = idx >> 5, c = idx & 31;
        int node = n0 + r;
        float v = 0.0f;
        if (node < nrows) {
            if (jobtype == 0)      v = (node < N_NET) ? net_feat[node * 32 + c]
                                                      : hanna_feat[(node - N_NET) * 32 + c];
            else if (jobtype == 1) v = node_feat[node * 32 + c];
            else if (jobtype == 2) v = hanna_feat[node * 32 + c];
            else                   v = net_feat[node * 32 + c];
        }
        Asm2[r * 33 + c] = f2pack(v, v);
    }

    // ---- stage W pairs ----
    int npairs = (jobtype == 0) ? ((grp < 4) ? 64 : 16) : (jobtype == 1) ? 32 : 16;
    for (int idx = tid; idx < 32 * npairs; idx += 256) {
        int i = idx / npairs, p = idx % npairs;
        float2 w;
        if (jobtype == 0) {
            if (grp < 4) {
                int slot = grp * 4 + (p >> 4);
                w = *(const float2*)&W_topo[slot * 1024 + i * 32 + (p & 15) * 2];
            } else {
                w = *(const float2*)&b_topo[i * 32 + p * 2];
            }
        } else if (jobtype == 1) {
            w = (p < 16) ? *(const float2*)&W_pins[i * 32 + p * 2]
                         : *(const float2*)&W_pt[i * 32 + (p - 16) * 2];
        } else if (jobtype == 2) {
            w = *(const float2*)&W_connect[i * 32 + p * 2];
        } else {
            w = *(const float2*)&W_net[i * 32 + p * 2];
        }
        Wsm2[i * npairs + p] = f2pack(w.x, w.y);
    }
    __syncthreads();

    // ---- compute + store ----
    if (jobtype == 0 && grp < 4) {
        int tx = tid & 31, ty = tid >> 5;
        ull acc[4][2] = {};
#pragma unroll
        for (int i = 0; i < 32; i++) {
            ull w0 = Wsm2[i * 64 + tx];
            ull w1 = Wsm2[i * 64 + 32 + tx];
#pragma unroll
            for (int r = 0; r < 4; r++) {
                ull a = Asm2[(ty * 4 + r) * 33 + i];
                acc[r][0] = ffma2(a, w0, acc[r][0]);
                acc[r][1] = ffma2(a, w1, acc[r][1]);
            }
        }
#pragma unroll
        for (int r = 0; r < 4; r++) {
            int node = n0 + ty * 4 + r;
            if (node >= N_PTOT) break;
            float lo, hi;
            f2unpack(acc[r][0], lo, hi);
            *(__half2*)&g_P[(size_t)node * 544 + grp * 128 + tx * 2] = __floats2half2_rn(lo, hi);
            f2unpack(acc[r][1], lo, hi);
            *(__half2*)&g_P[(size_t)node * 544 + grp * 128 + 64 + tx * 2] = __floats2half2_rn(lo, hi);
        }
    } else if (jobtype == 1) {
        int tx = tid & 31, ty = tid >> 5;
        ull acc[4] = {};
#pragma unroll
        for (int i = 0; i < 32; i++) {
            ull w = Wsm2[i * 32 + tx];
#pragma unroll
            for (int r = 0; r < 4; r++)
                acc[r] = ffma2(Asm2[(ty * 4 + r) * 33 + i], w, acc[r]);
        }
#pragma unroll
        for (int r = 0; r < 4; r++) {
            int node = n0 + ty * 4 + r;
            if (node >= N_CELL) break;
            float lo, hi;
            f2unpack(acc[r], lo, hi);
            if (tx < 16) *(float2*)&g_feat_pins[node * 32 + tx * 2]        = make_float2(lo, hi);
            else         *(float2*)&g_feat_pt[node * 32 + (tx - 16) * 2]   = make_float2(lo, hi);
        }
    } else {
        int tx = tid & 15, tyy = tid >> 4;
        ull acc[2] = {};
#pragma unroll
        for (int i = 0; i < 32; i++) {
            ull w = Wsm2[i * 16 + tx];
            acc[0] = ffma2(Asm2[(tyy * 2 + 0) * 33 + i], w, acc[0]);
            acc[1] = ffma2(Asm2[(tyy * 2 + 1) * 33 + i], w, acc[1]);
        }
#pragma unroll
        for (int r = 0; r < 2; r++) {
            int node = n0 + tyy * 2 + r;
            if (node >= nrows) break;
            float lo, hi;
            f2unpack(acc[r], lo, hi);
            if (jobtype == 0) {
                *(__half2*)&g_P[(size_t)node * 544 + 512 + tx * 2] = __floats2half2_rn(lo, hi);
            } else if (jobtype == 2) {
                *(float2*)&g_feat_connect[node * 32 + tx * 2] = make_float2(lo, hi);
            } else {
                // full overwrite of out_net incl. biases (no init dependency)
                float2 bb = make_float2(b_pins[tx * 2] + b_net[tx * 2],
                                        b_pins[tx * 2 + 1] + b_net[tx * 2 + 1]);
                *(float2*)&out_net[node * 32 + tx * 2] = make_float2(lo + bb.x, hi + bb.y);
            }
        }
    }
}

// ---------------------------------------------------------------------------
// K3: all 5 edge relations, 4 edges/warp (8 lanes/edge).
// GraphConv: out[dst] += feat[src] * rsqrt(ds) * rsqrt(dd)         (float4 + red.v4)
// NNConv:    16B P loads; lanes q<4 accumulate even k (incl bias), q>=4 odd k;
//            both halves issue partial red.v4 pairs (atomics commute).
__global__ __launch_bounds__(256) void edge_kernel(
        const int* __restrict__ pins_src, const int* __restrict__ pins_dst,
        const int* __restrict__ con_src,  const int* __restrict__ con_dst,
        const int* __restrict__ pt_src,   const int* __restrict__ pt_dst,
        const int* __restrict__ pinned_src, const int* __restrict__ pinned_dst,
        const int* __restrict__ pf_src,   const int* __restrict__ pf_dst,
        const float* __restrict__ pin_feat, const float* __restrict__ edge_feat,
        float* __restrict__ out_cell, float* __restrict__ out_net, float* __restrict__ out_gcell) {
    int t = blockIdx.x * blockDim.x + threadIdx.x;
    int lane = t & 31;
    int e = ((t >> 5) << 2) + (lane >> 3);     // 4 edges per warp
    if (e >= E) return;
    int q = lane & 7;
    int baseLane = lane & 24;
    int g = q >> 2;          // 0: even k (+bias), 1: odd k
    int c4 = q & 3;          // 8-col chunk

    // ---- all indices up front (max MLP) ----
    int s1 = pins_src[e],   d1 = pins_dst[e];
    int s2 = con_src[e],    d2 = con_dst[e];
    int s3 = pt_src[e],     d3 = pt_dst[e];
    int sA = pinned_src[e], dA = pinned_dst[e];
    int sB = pf_src[e] + N_NET, dB = pf_dst[e];

    float sc1 = rsqrtf((float)max(__ldg(&g_deg[OFF_PINS_S + s1]), 1)) *
                rsqrtf((float)max(__ldg(&g_deg[OFF_PINS_D + d1]), 1));
    float sc2 = rsqrtf((float)max(__ldg(&g_deg[OFF_CON_S + s2]), 1)) *
                rsqrtf((float)max(__ldg(&g_deg[OFF_CON_D + d2]), 1));
    float sc3 = rsqrtf((float)max(__ldg(&g_deg[OFF_PT_S + s3]), 1)) *
                rsqrtf((float)max(__ldg(&g_deg[OFF_PT_D + d3]), 1));
    float invA = 1.0f / (float)max(__ldg(&g_deg[OFF_PINNED_D + dA]), 1);
    float invB = 1.0f / (float)max(__ldg(&g_deg[OFF_PF_D + dB]), 1);

    float evA0 = pin_feat[e * 16 + q],  evA1 = pin_feat[e * 16 + 8 + q];
    float evB0 = edge_feat[e * 16 + q], evB1 = edge_feat[e * 16 + 8 + q];

    // ---- GraphConv gathers ----
    float4 v1 = *reinterpret_cast<const float4*>(&g_feat_pins[s1 * 32 + q * 4]);
    float4 v2 = *reinterpret_cast<const float4*>(&g_feat_connect[s2 * 32 + q * 4]);
    float4 v3 = *reinterpret_cast<const float4*>(&g_feat_pt[s3 * 32 + q * 4]);

    // ---- NNConv accumulation (ffma2, 16B loads) ----
    const __half* PA = g_P + (size_t)sA * 544;
    const __half* PB = g_P + (size_t)sB * 544;

    F8 accA, accB;
    if (g == 0) { accA = ldh8(PA + 512 + c4 * 8); accB = ldh8(PB + 512 + c4 * 8); }
    else {
#pragma unroll
        for (int i = 0; i < 4; i++) { accA.v[i] = 0ull; accB.v[i] = 0ull; }
    }

#pragma unroll
    for (int kk = 0; kk < 8; kk++) {
        int k = kk * 2 + g;
        float cA = __shfl_sync(0xffffffffu, (kk < 4) ? evA0 : evA1, baseLane + (k & 7));
        float cB = __shfl_sync(0xffffffffu, (kk < 4) ? evB0 : evB1, baseLane + (k & 7));
        ull ccA = f2pack(cA, cA);
        ull ccB = f2pack(cB, cB);
        F8 pa = ldh8(PA + k * 32 + c4 * 8);
        F8 pb = ldh8(PB + k * 32 + c4 * 8);
#pragma unroll
        for (int i = 0; i < 4; i++) {
            accA.v[i] = ffma2(pa.v[i], ccA, accA.v[i]);
            accB.v[i] = ffma2(pb.v[i], ccB, accB.v[i]);
        }
    }

    // ---- all reductions at the end ----
    red_add_v4(out_net   + d1 * 32 + q * 4, v1.x * sc1, v1.y * sc1, v1.z * sc1, v1.w * sc1);
    red_add_v4(out_gcell + d2 * 32 + q * 4, v2.x * sc2, v2.y * sc2, v2.z * sc2, v2.w * sc2);
    red_add_v4(out_gcell + d3 * 32 + q * 4, v3.x * sc3, v3.y * sc3, v3.z * sc3, v3.w * sc3);

    float a0, a1, a2, a3, a4, a5, a6, a7;
    f2unpack(accA.v[0], a0, a1); f2unpack(accA.v[1], a2, a3);
    f2unpack(accA.v[2], a4, a5); f2unpack(accA.v[3], a6, a7);
    red_add_v4(out_cell + dA * 32 + c4 * 8,     a0 * invA, a1 * invA, a2 * invA, a3 * invA);
    red_add_v4(out_cell + dA * 32 + c4 * 8 + 4, a4 * invA, a5 * invA, a6 * invA, a7 * invA);

    f2unpack(accB.v[0], a0, a1); f2unpack(accB.v[1], a2, a3);
    f2unpack(accB.v[2], a4, a5); f2unpack(accB.v[3], a6, a7);
    red_add_v4(out_cell + dB * 32 + c4 * 8,     a0 * invB, a1 * invB, a2 * invB, a3 * invB);
    red_add_v4(out_cell + dB * 32 + c4 * 8 + 4, a4 * invB, a5 * invB, a6 * invB, a7 * invB);
}

// ---------------------------------------------------------------------------
extern "C" void kernel_launch(void* const* d_in, const int* in_sizes, int n_in,
                              void* d_out, int out_size) {
    const float* node_feat   = (const float*)d_in[0];
    const float* net_feat    = (const float*)d_in[1];
    const float* pin_feat    = (const float*)d_in[2];
    const float* hanna_feat  = (const float*)d_in[3];
    const float* edge_feat   = (const float*)d_in[4];
    const int*   pins_src    = (const int*)d_in[5];
    const int*   pins_dst    = (const int*)d_in[6];
    const int*   pinned_src  = (const int*)d_in[7];
    const int*   pinned_dst  = (const int*)d_in[8];
    const int*   connect_src = (const int*)d_in[9];
    const int*   connect_dst = (const int*)d_in[10];
    const int*   pt_src      = (const int*)d_in[11];
    const int*   pt_dst      = (const int*)d_in[12];
    const int*   pf_src      = (const int*)d_in[13];
    const int*   pf_dst      = (const int*)d_in[14];
    const float* W_net       = (const float*)d_in[15];
    const float* b_net       = (const float*)d_in[16];
    const float* W_topo      = (const float*)d_in[17];
    const float* b_topo      = (const float*)d_in[18];
    const float* W_pins      = (const float*)d_in[19];
    const float* b_pins      = (const float*)d_in[20];
    const float* W_connect   = (const float*)d_in[21];
    const float* b_connect   = (const float*)d_in[22];
    const float* W_pt        = (const float*)d_in[23];
    const float* b_pt        = (const float*)d_in[24];
    const float* b_pinned    = (const float*)d_in[25];
    const float* b_pf        = (const float*)d_in[26];

    float* out       = (float*)d_out;
    float* out_net   = out + (size_t)N_CELL * D;
    float* out_gcell = out + (size_t)(N_CELL + N_NET) * D;

    // K1: zero degrees + bias-init cell/gcell output regions
    init_kernel<<<(INIT_TOTAL + 255) / 256, 256>>>(out, b_pinned, b_pf, b_connect, b_pt);

    // K2: degree counting + all dense GEMMs in one launch
    work_kernel<<<NB_WORK, 256>>>(node_feat, net_feat, hanna_feat,
                                  W_topo, b_topo, W_pins, W_pt, W_connect, W_net,
                                  b_pins, b_net,
                                  pins_src, pins_dst, connect_src, connect_dst,
                                  pt_src, pt_dst, pinned_dst, pf_dst, out_net);

    // K3: all 5 edge relations
    const int EGRID = (E / 4 * 32 + 255) / 256;   // 3125 blocks
    edge_kernel<<<EGRID, 256>>>(pins_src, pins_dst, connect_src, connect_dst,
                                pt_src, pt_dst, pinned_src, pinned_dst, pf_src, pf_dst,
                                pin_feat, edge_feat, out, out_net, out_gcell);
}